// round 4
// baseline (speedup 1.0000x reference)
#include <cuda_runtime.h>

#define FDIM 128
#define F4   32            // FDIM/4
#define BMAX 2048
#define NMAX 1100000
#define NCTA 592           // chunk CTAs for count/scatter (4 waves of 148)
#define EPSC 1e-3f

// ---- scratch (device globals; no allocations allowed) ----
__device__ int   g_is64;                   // 1 if graph_id is int64, 0 if int32
__device__ int   g_gid32[NMAX];            // converted ids
__device__ int   g_blockcnt[NCTA * BMAX];  // per-(CTA,graph) counts -> prefixes
__device__ int   g_counts[BMAX];           // per-graph totals
__device__ int   g_offsets[BMAX + 1];      // per-graph base offsets
__device__ int   g_perm[NMAX];             // node ids sorted by graph
__device__ float g_scale[BMAX * FDIM];
__device__ float g_shift[BMAX * FDIM];

__device__ __forceinline__ int load_gid(const void* gid, int i, int is64, int B) {
    int g = is64 ? (int)((const long long*)gid)[i] : ((const int*)gid)[i];
    return (g < 0) ? 0 : (g >= B ? B - 1 : g);   // defensive clamp
}

// ---- pass 0: probe gid dtype ----
__global__ void gn_init_kernel(const void* gid, int N, int B) {
    __shared__ int bad;
    if (threadIdx.x == 0) bad = 0;
    __syncthreads();
    int probe = N / 2;
    if (probe > 4096) probe = 4096;
    const long long* g64 = (const long long*)gid;
    for (int i = threadIdx.x; i < probe; i += blockDim.x) {
        long long v = g64[i];
        if (v < 0 || v >= (long long)B) bad = 1;
    }
    __syncthreads();
    if (threadIdx.x == 0) g_is64 = bad ? 0 : 1;
}

// ---- pass 1: convert gid -> int32 + per-CTA smem histogram (no global atomics) ----
__global__ __launch_bounds__(256) void gn_count_kernel(const void* __restrict__ gid,
                                                       int N, int B) {
    __shared__ int sh[BMAX];
    for (int i = threadIdx.x; i < B; i += 256) sh[i] = 0;
    __syncthreads();
    int is64  = g_is64;
    int chunk = (N + NCTA - 1) / NCTA;
    int s = blockIdx.x * chunk;
    int e = s + chunk; if (e > N) e = N;
    for (int i = s + threadIdx.x; i < e; i += 256) {
        int g = load_gid(gid, i, is64, B);
        g_gid32[i] = g;
        atomicAdd(&sh[g], 1);
    }
    __syncthreads();
    for (int i = threadIdx.x; i < B; i += 256)
        g_blockcnt[blockIdx.x * BMAX + i] = sh[i];
}

// ---- pass 2a: per-graph column prefix over CTAs + totals ----
__global__ void gn_colscan_kernel(int B) {
    int g = blockIdx.x * blockDim.x + threadIdx.x;
    if (g >= B) return;
    int acc = 0;
    for (int c = 0; c < NCTA; c++) {
        int v = g_blockcnt[c * BMAX + g];
        g_blockcnt[c * BMAX + g] = acc;   // exclusive within-graph prefix
        acc += v;
    }
    g_counts[g] = acc;
}

// ---- pass 2b: exclusive scan over per-graph totals (1 CTA, 1024 thr) ----
__global__ void gn_scan_kernel(int B) {
    __shared__ int tot[BMAX];
    __shared__ int ps[1024];
    int t = threadIdx.x;
    for (int i = t; i < BMAX; i += 1024) tot[i] = (i < B) ? g_counts[i] : 0;
    __syncthreads();
    int a = tot[2 * t];
    int b = tot[2 * t + 1];
    ps[t] = a + b;
    __syncthreads();
    for (int off = 1; off < 1024; off <<= 1) {
        int v = ps[t];
        int add = (t >= off) ? ps[t - off] : 0;
        __syncthreads();
        ps[t] = v + add;
        __syncthreads();
    }
    int excl = (t > 0) ? ps[t - 1] : 0;
    g_offsets[2 * t]     = excl;
    g_offsets[2 * t + 1] = excl + a;
    if (t == 1023) g_offsets[BMAX] = ps[1023];
}

// ---- pass 3: scatter with smem cursors (no global atomics) ----
__global__ __launch_bounds__(256) void gn_scatter_kernel(int N, int B) {
    __shared__ int cur[BMAX];
    for (int i = threadIdx.x; i < B; i += 256)
        cur[i] = g_offsets[i] + g_blockcnt[blockIdx.x * BMAX + i];
    __syncthreads();
    int chunk = (N + NCTA - 1) / NCTA;
    int s = blockIdx.x * chunk;
    int e = s + chunk; if (e > N) e = N;
    for (int i = s + threadIdx.x; i < e; i += 256) {
        int g   = g_gid32[i];
        int pos = atomicAdd(&cur[g], 1);
        g_perm[pos] = i;
    }
}

// ---- pass 4: per-graph moments -> scale/shift (1 CTA per graph, 8 warps) ----
__global__ __launch_bounds__(256) void gn_stats_kernel(const float* __restrict__ values,
                                                       const float* __restrict__ gamma,
                                                       const float* __restrict__ beta,
                                                       const float* __restrict__ alpha) {
    __shared__ int    idx[2048];
    __shared__ float4 ss[8][F4];
    __shared__ float4 sq[8][F4];

    int b     = blockIdx.x;
    int start = g_offsets[b];
    int end   = g_offsets[b + 1];
    int c     = end - start;
    int w     = threadIdx.x >> 5;
    int lane  = threadIdx.x & 31;

    const float4* v4 = (const float4*)values;

    float4 s = make_float4(0.f, 0.f, 0.f, 0.f);
    float4 q = make_float4(0.f, 0.f, 0.f, 0.f);

    for (int ts = start; ts < end; ts += 2048) {
        int tn = end - ts; if (tn > 2048) tn = 2048;
        __syncthreads();
        for (int i = threadIdx.x; i < tn; i += 256) idx[i] = g_perm[ts + i];
        __syncthreads();
        // node indices now in smem -> value loads are independent (high MLP)
        for (int r = w; r < tn; r += 8) {
            float4 v = __ldg(&v4[(size_t)idx[r] * F4 + lane]);
            s.x += v.x; s.y += v.y; s.z += v.z; s.w += v.w;
            q.x = fmaf(v.x, v.x, q.x);
            q.y = fmaf(v.y, v.y, q.y);
            q.z = fmaf(v.z, v.z, q.z);
            q.w = fmaf(v.w, v.w, q.w);
        }
    }

    ss[w][lane] = s;
    sq[w][lane] = q;
    __syncthreads();

    int f = threadIdx.x;
    if (f < FDIM) {
        const float* ssf = (const float*)ss;   // [8][128] floats
        const float* sqf = (const float*)sq;
        float S = 0.f, Q = 0.f;
#pragma unroll
        for (int i = 0; i < 8; i++) {
            S += ssf[i * FDIM + f];
            Q += sqf[i * FDIM + f];
        }
        float inv  = (c > 0) ? (1.0f / (float)c) : 0.0f;
        float m    = S * inv;
        float m2   = Q * inv;
        float msh  = m * alpha[f];
        float var  = m2 - 2.0f * msh * m + msh * msh;
        float rstd = rsqrtf(var + EPSC);
        float sc   = gamma[f] * rstd;
        g_scale[b * FDIM + f] = sc;
        g_shift[b * FDIM + f] = beta[f] - msh * sc;
    }
}

// ---- pass 5: normalize, streaming in natural node order (warp-per-row) ----
__global__ __launch_bounds__(256) void gn_norm_kernel(const float* __restrict__ values,
                                                      float* __restrict__ out,
                                                      int N) {
    int w    = threadIdx.x >> 5;
    int lane = threadIdx.x & 31;
    int rows_per_step = gridDim.x * 8;

    const float4* v4  = (const float4*)values;
    const float4* sc4 = (const float4*)g_scale;
    const float4* sh4 = (const float4*)g_shift;
    float4*       o4  = (float4*)out;

    for (int node = blockIdx.x * 8 + w; node < N; node += rows_per_step) {
        int    b   = g_gid32[node];
        size_t idx = (size_t)node * F4 + lane;
        float4 v  = __ldg(&v4[idx]);
        float4 sc = __ldg(&sc4[b * F4 + lane]);
        float4 sh = __ldg(&sh4[b * F4 + lane]);
        float4 o;
        o.x = fmaf(v.x, sc.x, sh.x);
        o.y = fmaf(v.y, sc.y, sh.y);
        o.z = fmaf(v.z, sc.z, sh.z);
        o.w = fmaf(v.w, sc.w, sh.w);
        o4[idx] = o;
    }
}

extern "C" void kernel_launch(void* const* d_in, const int* in_sizes, int n_in,
                              void* d_out, int out_size) {
    const float* values = (const float*)d_in[0];
    const void*  gid    = d_in[1];
    // d_in[2] = reference_ids (only its length B is needed)
    const float* gamma  = (const float*)d_in[3];
    const float* beta   = (const float*)d_in[4];
    const float* alpha  = (const float*)d_in[5];

    int N = in_sizes[0] / FDIM;
    int B = in_sizes[2];
    if (B > BMAX) B = BMAX;
    if (B < 1)    B = 1;

    gn_init_kernel<<<1, 256>>>(gid, N, B);
    gn_count_kernel<<<NCTA, 256>>>(gid, N, B);
    gn_colscan_kernel<<<(B + 127) / 128, 128>>>(B);
    gn_scan_kernel<<<1, 1024>>>(B);
    gn_scatter_kernel<<<NCTA, 256>>>(N, B);
    gn_stats_kernel<<<B, 256>>>(values, gamma, beta, alpha);
    gn_norm_kernel<<<2432, 256>>>(values, (float*)d_out, N);
}

// round 5
// speedup vs baseline: 1.3343x; 1.3343x over previous
#include <cuda_runtime.h>

#define FDIM 128
#define F4   32              // FDIM/4
#define BMAX 2048
#define NMAX 1100000
#define NCTA 148             // one wave for count/scatter
#define TILE 4096            // idx staging tile (rows)
#define EPSC 1e-3f

// ---- scratch (device globals; no allocations allowed) ----
__device__ int g_gid32[NMAX];            // converted ids
__device__ int g_blockcnt[NCTA * BMAX];  // per-(CTA,graph) counts -> prefixes
__device__ int g_offsets[BMAX + 1];      // per-graph base offsets
__device__ int g_perm[NMAX];             // node ids sorted by graph

// ---- pass 1: dtype probe + convert gid -> int32 + per-CTA histogram ----
__global__ __launch_bounds__(256) void gn_count_kernel(const void* __restrict__ gid,
                                                       int N, int B) {
    __shared__ int sh[BMAX];
    __shared__ int s_is64;
    for (int i = threadIdx.x; i < B; i += 256) sh[i] = 0;
    if (threadIdx.x == 0) s_is64 = 1;
    __syncthreads();

    int chunk = (N + NCTA - 1) / NCTA;
    int s = blockIdx.x * chunk;
    int e = s + chunk; if (e > N) e = N;

    // local dtype probe: view this CTA's chunk as int64; any out-of-range -> int32
    {
        int probe = (e - s) / 2;
        if (probe > 512) probe = 512;
        const long long* g64 = (const long long*)gid + (s / 2);
        for (int i = threadIdx.x; i < probe; i += 256) {
            long long v = g64[i];
            if (v < 0 || v >= (long long)B) s_is64 = 0;
        }
    }
    __syncthreads();
    int is64 = s_is64;

    for (int i = s + threadIdx.x; i < e; i += 256) {
        int g = is64 ? (int)((const long long*)gid)[i] : ((const int*)gid)[i];
        g = (g < 0) ? 0 : (g >= B ? B - 1 : g);
        g_gid32[i] = g;
        atomicAdd(&sh[g], 1);
    }
    __syncthreads();
    for (int i = threadIdx.x; i < B; i += 256)
        g_blockcnt[blockIdx.x * BMAX + i] = sh[i];
}

// ---- pass 2: column prefix over CTAs + exclusive scan over graph totals ----
__global__ __launch_bounds__(1024) void gn_offsets_kernel(int B) {
    __shared__ int tot[BMAX];
    __shared__ int ps[1024];
    int t = threadIdx.x;

    // column prefix: for each graph, exclusive prefix across the NCTA chunks
    for (int g = t; g < BMAX; g += 1024) {
        int acc = 0;
        if (g < B) {
            for (int c = 0; c < NCTA; c++) {
                int v = g_blockcnt[c * BMAX + g];
                g_blockcnt[c * BMAX + g] = acc;
                acc += v;
            }
        }
        tot[g] = acc;
    }
    __syncthreads();

    // exclusive scan over 2048 totals (2 per thread, Hillis-Steele)
    int a = tot[2 * t];
    int b = tot[2 * t + 1];
    ps[t] = a + b;
    __syncthreads();
    for (int off = 1; off < 1024; off <<= 1) {
        int v = ps[t];
        int add = (t >= off) ? ps[t - off] : 0;
        __syncthreads();
        ps[t] = v + add;
        __syncthreads();
    }
    int excl = (t > 0) ? ps[t - 1] : 0;
    g_offsets[2 * t]     = excl;
    g_offsets[2 * t + 1] = excl + a;
    if (t == 1023) g_offsets[BMAX] = ps[1023];
}

// ---- pass 3: scatter with smem cursors (stable within chunk order) ----
__global__ __launch_bounds__(256) void gn_scatter_kernel(int N, int B) {
    __shared__ int cur[BMAX];
    for (int i = threadIdx.x; i < B; i += 256)
        cur[i] = g_offsets[i] + g_blockcnt[blockIdx.x * BMAX + i];
    __syncthreads();
    int chunk = (N + NCTA - 1) / NCTA;
    int s = blockIdx.x * chunk;
    int e = s + chunk; if (e > N) e = N;
    for (int i = s + threadIdx.x; i < e; i += 256) {
        int g   = g_gid32[i];
        int pos = atomicAdd(&cur[g], 1);
        g_perm[pos] = i;
    }
}

// ---- pass 4: FUSED stats + normalize. 1 CTA (1024 thr / 32 warps) per graph.
// loop1 gathers rows and computes moments; loop2 re-reads the same rows
// (L2-resident: ~250KB/graph x 2 CTAs/SM x 148 SMs ~ 74MB < 126MB L2),
// normalizes, writes out. values is read from DRAM only once.
__global__ __launch_bounds__(1024, 1) void gn_fused_kernel(const float* __restrict__ values,
                                                           const float* __restrict__ gamma,
                                                           const float* __restrict__ beta,
                                                           const float* __restrict__ alpha,
                                                           float* __restrict__ out) {
    __shared__ int   idx[TILE];
    __shared__ float ss[32 * FDIM];   // per-warp partial sums
    __shared__ float sq[32 * FDIM];   // per-warp partial sumsq
    __shared__ float scs[FDIM];
    __shared__ float shs[FDIM];

    int b     = blockIdx.x;
    int start = g_offsets[b];
    int end   = g_offsets[b + 1];
    int c     = end - start;
    if (c == 0) return;                 // uniform per CTA

    int w    = threadIdx.x >> 5;        // 0..31
    int lane = threadIdx.x & 31;

    const float4* v4 = (const float4*)values;
    float4*       o4 = (float4*)out;

    float4 s = make_float4(0.f, 0.f, 0.f, 0.f);
    float4 q = make_float4(0.f, 0.f, 0.f, 0.f);

    // ---- loop1: gather + moments ----
    for (int ts = start; ts < end; ts += TILE) {
        int tn = end - ts; if (tn > TILE) tn = TILE;
        __syncthreads();
        for (int i = threadIdx.x; i < tn; i += 1024) idx[i] = g_perm[ts + i];
        __syncthreads();
        for (int r = w; r < tn; r += 32) {
            float4 v = __ldg(&v4[(size_t)idx[r] * F4 + lane]);
            s.x += v.x; s.y += v.y; s.z += v.z; s.w += v.w;
            q.x = fmaf(v.x, v.x, q.x);
            q.y = fmaf(v.y, v.y, q.y);
            q.z = fmaf(v.z, v.z, q.z);
            q.w = fmaf(v.w, v.w, q.w);
        }
    }

    ((float4*)ss)[w * F4 + lane] = s;
    ((float4*)sq)[w * F4 + lane] = q;
    __syncthreads();

    // ---- reduce 32 partials, compute scale/shift ----
    int f = threadIdx.x;
    if (f < FDIM) {
        float S = 0.f, Q = 0.f;
#pragma unroll
        for (int i = 0; i < 32; i++) {
            S += ss[i * FDIM + f];
            Q += sq[i * FDIM + f];
        }
        float inv  = 1.0f / (float)c;
        float m    = S * inv;
        float m2   = Q * inv;
        float msh  = m * alpha[f];                    // shifted mean
        float var  = m2 - 2.0f * msh * m + msh * msh; // E[(x - msh)^2]
        float rstd = rsqrtf(var + EPSC);
        float sc   = gamma[f] * rstd;
        scs[f] = sc;
        shs[f] = beta[f] - msh * sc;
    }
    __syncthreads();

    float4 sc4 = ((const float4*)scs)[lane];
    float4 sh4 = ((const float4*)shs)[lane];

    // ---- loop2: normalize (reads hit L2), write out ----
    for (int ts = start; ts < end; ts += TILE) {
        int tn = end - ts; if (tn > TILE) tn = TILE;
        if (c > TILE) {                     // re-stage only if >1 tile
            __syncthreads();
            for (int i = threadIdx.x; i < tn; i += 1024) idx[i] = g_perm[ts + i];
            __syncthreads();
        }
        for (int r = w; r < tn; r += 32) {
            size_t gi = (size_t)idx[r] * F4 + lane;
            float4 v  = __ldg(&v4[gi]);
            float4 o;
            o.x = fmaf(v.x, sc4.x, sh4.x);
            o.y = fmaf(v.y, sc4.y, sh4.y);
            o.z = fmaf(v.z, sc4.z, sh4.z);
            o.w = fmaf(v.w, sc4.w, sh4.w);
            o4[gi] = o;
        }
    }
}

extern "C" void kernel_launch(void* const* d_in, const int* in_sizes, int n_in,
                              void* d_out, int out_size) {
    const float* values = (const float*)d_in[0];
    const void*  gid    = d_in[1];
    // d_in[2] = reference_ids (only its length B is needed)
    const float* gamma  = (const float*)d_in[3];
    const float* beta   = (const float*)d_in[4];
    const float* alpha  = (const float*)d_in[5];

    int N = in_sizes[0] / FDIM;
    int B = in_sizes[2];
    if (B > BMAX) B = BMAX;
    if (B < 1)    B = 1;

    gn_count_kernel<<<NCTA, 256>>>(gid, N, B);
    gn_offsets_kernel<<<1, 1024>>>(B);
    gn_scatter_kernel<<<NCTA, 256>>>(N, B);
    gn_fused_kernel<<<B, 1024>>>(values, gamma, beta, alpha, (float*)d_out);
}